// round 1
// baseline (speedup 1.0000x reference)
#include <cuda_runtime.h>

// PatchShuffle: RATIO=0.75, NUM_ROWS=16, NUM_COLS=64, T=1024, B=64, C=768, STRIPE_W=48
// Outputs (flat fp32, in tuple order):
//   visible       : 256*64*768 = 12,582,912
//   fwd           : 1024*64    =     65,536
//   bwd           : 1024*64    =     65,536
//   stripe_bounds : 2*64       =        128
// total out_size  = 12,714,112

#define NROWS    16
#define NCOLS    64
#define BATCH    64
#define CH       768
#define SW       48           // stripe width
#define NVIS     16           // NCOLS - SW (visible cols per row, also max start)
#define TVIS     256          // rows t in [0,256) are emitted as "visible"
#define ROW_F4   (CH/4)       // 192 float4 per (t,b) row
#define VIS_ELEMS (12582912LL)

// perm[b][j]: column order after moving stripe columns to the back.
__device__ __forceinline__ int perm_of(int j, int s) {
    // j in [0,64): first 16 = non-stripe cols ascending, last 48 = stripe cols ascending
    return (j < NVIS) ? ((j < s) ? j : j + SW) : (s + (j - NVIS));
}

__global__ void gather_visible(const float4* __restrict__ patches,
                               const int*    __restrict__ start_cols,
                               float4*       __restrict__ out) {
    // one float4 per thread; total = TVIS * BATCH * ROW_F4 = 3,145,728
    unsigned idx = blockIdx.x * blockDim.x + threadIdx.x;
    const unsigned total = (unsigned)TVIS * BATCH * ROW_F4;
    if (idx >= total) return;

    int lane = idx % ROW_F4;          // float4 index within the 768-float row
    int row  = idx / ROW_F4;          // row = t*64 + b, t in [0,256)
    int b    = row & 63;
    int t    = row >> 6;
    int j    = t & 63;                // column slot within shuffled row
    int r    = t >> 6;                // r in [0,4)
    int s    = __ldg(&start_cols[b]);
    int src_t = r * NCOLS + perm_of(j, s);

    // patches[(src_t, b, :)] -> out[(t, b, :)]
    out[(long)row * ROW_F4 + lane] =
        patches[((long)src_t * BATCH + b) * ROW_F4 + lane];
}

__global__ void write_indexes(const int* __restrict__ start_cols,
                              float*     __restrict__ out) {
    int idx = blockIdx.x * blockDim.x + threadIdx.x;
    // layout after visible: fwd[65536], bwd[65536], bounds[128]
    if (idx < 65536) {
        // fwd[t, b] with t = r*64 + j
        int b = idx & 63;
        int t = idx >> 6;
        int j = t & 63, r = t >> 6;
        int s = __ldg(&start_cols[b]);
        out[VIS_ELEMS + idx] = (float)(r * NCOLS + perm_of(j, s));
    } else if (idx < 131072) {
        // bwd[p, b] with p = r*64 + c ; bwd = inverse permutation of fwd per column
        int k = idx - 65536;
        int b = k & 63;
        int p = k >> 6;
        int c = p & 63, r = p >> 6;
        int s = __ldg(&start_cols[b]);
        int inv = (c < s) ? c : ((c < s + SW) ? (NVIS + c - s) : (c - SW));
        out[VIS_ELEMS + 65536 + k] = (float)(r * NCOLS + inv);
    } else if (idx < 131200) {
        // stripe_bounds: row 0 = start, row 1 = start + SW
        int k = idx - 131072;
        int b = k & 63;
        int s = __ldg(&start_cols[b]);
        out[VIS_ELEMS + 131072 + k] = (float)((k < 64) ? s : s + SW);
    }
}

extern "C" void kernel_launch(void* const* d_in, const int* in_sizes, int n_in,
                              void* d_out, int out_size) {
    const float4* patches    = (const float4*)d_in[0];
    const int*    start_cols = (const int*)d_in[1];
    float*        out        = (float*)d_out;

    const unsigned total_f4 = (unsigned)TVIS * BATCH * ROW_F4;   // 3,145,728
    const int threads = 256;
    gather_visible<<<(total_f4 + threads - 1) / threads, threads>>>(
        patches, start_cols, (float4*)out);

    write_indexes<<<(131200 + threads - 1) / threads, threads>>>(start_cols, out);
}

// round 2
// speedup vs baseline: 1.1194x; 1.1194x over previous
#include <cuda_runtime.h>

// PatchShuffle: RATIO=0.75, NUM_ROWS=16, NUM_COLS=64, T=1024, B=64, C=768, STRIPE_W=48
// Outputs (flat fp32, in tuple order):
//   visible       : 256*64*768 = 12,582,912
//   fwd           : 1024*64    =     65,536
//   bwd           : 1024*64    =     65,536
//   stripe_bounds : 2*64       =        128

#define NCOLS    64
#define BATCH    64
#define SW       48           // stripe width
#define NVIS     16           // NCOLS - SW
#define TVIS     256
#define ROW_F4   192          // 768/4 float4 per (t,b) row
#define VIS_ELEMS 12582912LL
#define TOTAL_F4 3145728u     // TVIS*BATCH*ROW_F4
#define IDX_WORK 131200u      // fwd + bwd + bounds elements

__device__ __forceinline__ int perm_of(int j, int s) {
    return (j < NVIS) ? ((j < s) ? j : j + SW) : (s + (j - NVIS));
}

__global__ void __launch_bounds__(256)
patch_shuffle_fused(const float4* __restrict__ patches,
                    const int*    __restrict__ start_cols,
                    float*        __restrict__ out) {
    unsigned idx = blockIdx.x * blockDim.x + threadIdx.x;

    if (idx < TOTAL_F4) {
        // ---- main gather: one float4 per thread ----
        int lane = idx % ROW_F4;
        int row  = idx / ROW_F4;        // row = t*64 + b, t in [0,256)
        int b    = row & 63;
        int t    = row >> 6;
        int j    = t & 63;
        int r    = t >> 6;
        int s    = __ldg(&start_cols[b]);
        int src_t = r * NCOLS + perm_of(j, s);
        ((float4*)out)[(long)row * ROW_F4 + lane] =
            patches[((long)src_t * BATCH + b) * ROW_F4 + lane];
        return;
    }

    unsigned k = idx - TOTAL_F4;
    if (k >= IDX_WORK) return;

    if (k < 65536) {
        // fwd[t, b]
        int b = k & 63;
        int t = k >> 6;
        int j = t & 63, r = t >> 6;
        int s = __ldg(&start_cols[b]);
        out[VIS_ELEMS + k] = (float)(r * NCOLS + perm_of(j, s));
    } else if (k < 131072) {
        // bwd[p, b]  (closed-form inverse permutation)
        unsigned m = k - 65536;
        int b = m & 63;
        int p = m >> 6;
        int c = p & 63, r = p >> 6;
        int s = __ldg(&start_cols[b]);
        int inv = (c < s) ? c : ((c < s + SW) ? (NVIS + c - s) : (c - SW));
        out[VIS_ELEMS + 65536 + m] = (float)(r * NCOLS + inv);
    } else {
        // stripe_bounds: row 0 = start, row 1 = start + SW
        unsigned m = k - 131072;
        int b = m & 63;
        int s = __ldg(&start_cols[b]);
        out[VIS_ELEMS + 131072 + m] = (float)((m < 64) ? s : s + SW);
    }
}

extern "C" void kernel_launch(void* const* d_in, const int* in_sizes, int n_in,
                              void* d_out, int out_size) {
    const float4* patches    = (const float4*)d_in[0];
    const int*    start_cols = (const int*)d_in[1];
    float*        out        = (float*)d_out;

    const unsigned total = TOTAL_F4 + IDX_WORK;   // 3,276,928
    const int threads = 256;
    patch_shuffle_fused<<<(total + threads - 1) / threads, threads>>>(
        patches, start_cols, out);
}

// round 3
// speedup vs baseline: 1.2959x; 1.1577x over previous
#include <cuda_runtime.h>

// PatchShuffle: RATIO=0.75, NUM_ROWS=16, NUM_COLS=64, T=1024, B=64, C=768, STRIPE_W=48
// Outputs (flat fp32, in tuple order):
//   visible       : 256*64*768 = 12,582,912
//   fwd           : 1024*64    =     65,536
//   bwd           : 1024*64    =     65,536
//   stripe_bounds : 2*64       =        128

#define NCOLS    64
#define BATCH    64
#define SW       48
#define NVIS     16
#define ROW_F4   192           // float4 per (t,b) row
#define VIS_ELEMS 12582912LL
#define NROWS_OUT 16384u       // TVIS * BATCH = 256*64 visible (t,b) rows
#define GATHER_BLOCKS 2048u    // NROWS_OUT / 8 warps per block
#define IDX_WORK 131200u
#define IDX_BLOCKS 513u        // ceil(131200/256)

__device__ __forceinline__ int perm_of(int j, int s) {
    return (j < NVIS) ? ((j < s) ? j : j + SW) : (s + (j - NVIS));
}

__global__ void __launch_bounds__(256)
patch_shuffle_fused(const float4* __restrict__ patches,
                    const int*    __restrict__ start_cols,
                    float*        __restrict__ out) {
    if (blockIdx.x < GATHER_BLOCKS) {
        // ---- gather: one warp per output row (256 visible t × 64 b) ----
        unsigned warp = blockIdx.x * 8 + (threadIdx.x >> 5);
        int lane = threadIdx.x & 31;
        int b = warp & 63;
        int t = warp >> 6;              // t in [0,256)
        int j = t & 63;
        int r = t >> 6;
        int s = __ldg(&start_cols[b]);
        int src_t = r * NCOLS + perm_of(j, s);

        const float4* src = patches + ((long)src_t * BATCH + b) * ROW_F4 + lane;
        float4*       dst = (float4*)out + (long)warp * ROW_F4 + lane;

        float4 v0 = src[0];
        float4 v1 = src[32];
        float4 v2 = src[64];
        float4 v3 = src[96];
        float4 v4 = src[128];
        float4 v5 = src[160];
        dst[0]   = v0;
        dst[32]  = v1;
        dst[64]  = v2;
        dst[96]  = v3;
        dst[128] = v4;
        dst[160] = v5;
        return;
    }

    // ---- index outputs: thread-per-element tail blocks ----
    unsigned k = (blockIdx.x - GATHER_BLOCKS) * blockDim.x + threadIdx.x;
    if (k >= IDX_WORK) return;

    if (k < 65536) {
        // fwd[t, b]
        int b = k & 63;
        int t = k >> 6;
        int j = t & 63, r = t >> 6;
        int s = __ldg(&start_cols[b]);
        out[VIS_ELEMS + k] = (float)(r * NCOLS + perm_of(j, s));
    } else if (k < 131072) {
        // bwd[p, b] (closed-form inverse)
        unsigned m = k - 65536;
        int b = m & 63;
        int p = m >> 6;
        int c = p & 63, r = p >> 6;
        int s = __ldg(&start_cols[b]);
        int inv = (c < s) ? c : ((c < s + SW) ? (NVIS + c - s) : (c - SW));
        out[VIS_ELEMS + 65536 + m] = (float)(r * NCOLS + inv);
    } else {
        unsigned m = k - 131072;
        int b = m & 63;
        int s = __ldg(&start_cols[b]);
        out[VIS_ELEMS + 131072 + m] = (float)((m < 64) ? s : s + SW);
    }
}

extern "C" void kernel_launch(void* const* d_in, const int* in_sizes, int n_in,
                              void* d_out, int out_size) {
    const float4* patches    = (const float4*)d_in[0];
    const int*    start_cols = (const int*)d_in[1];
    float*        out        = (float*)d_out;

    patch_shuffle_fused<<<GATHER_BLOCKS + IDX_BLOCKS, 256>>>(
        patches, start_cols, out);
}